// round 15
// baseline (speedup 1.0000x reference)
#include <cuda_runtime.h>
#include <cuda_bf16.h>
#include <cstdint>

#define T_LEN 4096
#define E_DIM 256
#define H_DIM 512
#define G4    2048
#define TAGS  50
#define NCTA  128

// ---------------- device scratch (no allocations allowed) ----------------
__device__ float g_Gx[2][(size_t)T_LEN * G4];            // x-proj, TRANSPOSED: [t][u][gate]
__device__ unsigned long long g_hp[2][T_LEN][H_DIM];     // packets {tag:32 | h:32}, t-major
__device__ unsigned g_epoch;                             // bumped once per launch

// ---------------- Kernel 1: Gx[dir][t][u*4+q] = (emb[sent[t]] @ W_ih^T + b)[q*512+u] ----
#define BM 64
#define BN 64
#define BK 16

__global__ __launch_bounds__(256) void xproj_kernel(
    const int* __restrict__ sent, const float* __restrict__ emb,
    const float* __restrict__ Wih_f, const float* __restrict__ bih_f, const float* __restrict__ bhh_f,
    const float* __restrict__ Wih_b, const float* __restrict__ bih_b, const float* __restrict__ bhh_b)
{
    const int dir = blockIdx.z;
    const float* __restrict__ Wih = dir ? Wih_b : Wih_f;
    const float* __restrict__ bih = dir ? bih_b : bih_f;
    const float* __restrict__ bhh = dir ? bhh_b : bhh_f;
    float* __restrict__ C = g_Gx[dir];

    // bump epoch once per launch (stream-ordered before the recurrence kernel)
    if (blockIdx.x == 0 && blockIdx.y == 0 && dir == 0 && threadIdx.x == 0) {
        g_epoch = g_epoch + 1u;
    }

    __shared__ float As[BK][BM + 4];
    __shared__ float Bs[BK][BN + 4];
    __shared__ int   sidx[BM];

    const int tid = threadIdx.x;
    const int tx = tid & 15;
    const int ty = tid >> 4;
    const int t0 = blockIdx.y * BM;
    const int n0 = blockIdx.x * BN;

    if (tid < BM) sidx[tid] = sent[t0 + tid];
    __syncthreads();

    float acc[4][4];
#pragma unroll
    for (int i = 0; i < 4; i++)
#pragma unroll
        for (int j = 0; j < 4; j++) acc[i][j] = 0.f;

    const int li = tid >> 2;
    const int lk = (tid & 3) * 4;

    for (int k0 = 0; k0 < E_DIM; k0 += BK) {
        const float4 av = *(const float4*)&emb[(size_t)sidx[li] * E_DIM + k0 + lk];
        const float4 bv = *(const float4*)&Wih[(size_t)(n0 + li) * E_DIM + k0 + lk];
        __syncthreads();
        As[lk + 0][li] = av.x; As[lk + 1][li] = av.y; As[lk + 2][li] = av.z; As[lk + 3][li] = av.w;
        Bs[lk + 0][li] = bv.x; Bs[lk + 1][li] = bv.y; Bs[lk + 2][li] = bv.z; Bs[lk + 3][li] = bv.w;
        __syncthreads();
#pragma unroll
        for (int kk = 0; kk < BK; kk++) {
            const float4 a = *(const float4*)&As[kk][ty * 4];
            const float4 b = *(const float4*)&Bs[kk][tx * 4];
            acc[0][0] = fmaf(a.x, b.x, acc[0][0]); acc[0][1] = fmaf(a.x, b.y, acc[0][1]);
            acc[0][2] = fmaf(a.x, b.z, acc[0][2]); acc[0][3] = fmaf(a.x, b.w, acc[0][3]);
            acc[1][0] = fmaf(a.y, b.x, acc[1][0]); acc[1][1] = fmaf(a.y, b.y, acc[1][1]);
            acc[1][2] = fmaf(a.y, b.z, acc[1][2]); acc[1][3] = fmaf(a.y, b.w, acc[1][3]);
            acc[2][0] = fmaf(a.z, b.x, acc[2][0]); acc[2][1] = fmaf(a.z, b.y, acc[2][1]);
            acc[2][2] = fmaf(a.z, b.z, acc[2][2]); acc[2][3] = fmaf(a.z, b.w, acc[2][3]);
            acc[3][0] = fmaf(a.w, b.x, acc[3][0]); acc[3][1] = fmaf(a.w, b.y, acc[3][1]);
            acc[3][2] = fmaf(a.w, b.z, acc[3][2]); acc[3][3] = fmaf(a.w, b.w, acc[3][3]);
        }
    }

    const int n_base = n0 + tx * 4;
    const int q = n_base >> 9;              // gate index (same for all 4 columns: 64 | 512)
    float4 bias;
    bias.x = bih[n_base + 0] + bhh[n_base + 0];
    bias.y = bih[n_base + 1] + bhh[n_base + 1];
    bias.z = bih[n_base + 2] + bhh[n_base + 2];
    bias.w = bih[n_base + 3] + bhh[n_base + 3];
    const int u_base = n_base & 511;
#pragma unroll
    for (int i = 0; i < 4; i++) {
        const int t = t0 + ty * 4 + i;
        float* ct = &C[(size_t)t * G4 + (size_t)u_base * 4 + q];
        ct[0]  = acc[i][0] + bias.x;
        ct[4]  = acc[i][1] + bias.y;
        ct[8]  = acc[i][2] + bias.z;
        ct[12] = acc[i][3] + bias.w;
    }
}

// ---------------- dummy kernel: shifts ncu -s5 capture window onto lstm_rec -------------
__global__ void align_dummy_kernel() {}

// ---------------- Kernel 2: persistent recurrence, BARRIER-FREE tagged-SMEM dataflow ----
// R7's exact layout/traffic/math; both __syncthreads replaced by per-word {tag|value}
// SMEM packets (aligned 8B volatile = single-copy atomic; tag and data in one word).
// sigm(x) = 1/(1+e^-x); tanh(x) = 2*sigm(2x)-1
__device__ __forceinline__ float sigmf(float x) { return 1.f / (1.f + __expf(-x)); }

__global__ __launch_bounds__(512, 1) void lstm_rec_kernel(
    const float* __restrict__ Whhf, const float* __restrict__ Whhb)
{
    const int tid  = threadIdx.x;
    const int lane = tid & 31;
    const int w    = tid >> 5;        // 16 warps
    const int bid  = blockIdx.x;
    const int dir  = bid >> 6;        // 0 = forward, 1 = backward
    const int s    = bid & 63;
    const int u0   = s << 3;          // first of 8 hidden units owned by this CTA

    const float* __restrict__ Whh = dir ? Whhb : Whhf;
    const float* __restrict__ Gx  = g_Gx[dir];

    const unsigned epoch = *((volatile unsigned*)&g_epoch);
    const unsigned tagbase = epoch * 8192u;      // global h tags: tagbase+t; zero-tag: +8191

    __shared__ unsigned long long h_s8[2][H_DIM];   // tagged h packets (double-buffered)
    __shared__ unsigned long long gates_s8[32];     // tagged gate sums {step+1 | gate}

    // init SMEM tags (garbage protection); the ONLY block barrier in the kernel
    ((volatile unsigned long long*)h_s8[0])[tid] = 0ull;
    ((volatile unsigned long long*)h_s8[1])[tid] = 0ull;
    if (tid < 32) ((volatile unsigned long long*)gates_s8)[tid] = 0ull;
    __syncthreads();

    // warp w owns rows idx = w*2 + r, r in {0,1}; gate q = idx>>3; unit j = idx&7
    const int idx0 = w * 2;
    int rows[2];
#pragma unroll
    for (int r = 0; r < 2; r++) {
        const int idx = idx0 + r;
        rows[r] = (idx >> 3) * H_DIM + u0 + (idx & 7);
    }
    float wr0[16], wr1[16];
#pragma unroll
    for (int jj = 0; jj < 16; jj++) {
        wr0[jj] = __ldg(&Whh[(size_t)rows[0] * H_DIM + lane + 32 * jj]);
        wr1[jj] = __ldg(&Whh[(size_t)rows[1] * H_DIM + lane + 32 * jj]);
    }
    // transposed-Gx address for this warp's row r: t*2048 + (u0+(idx&7))*4 + (idx>>3)
    int gxoff = -1;
    if (lane < 2) {
        const int idx = idx0 + lane;
        gxoff = (u0 + (idx & 7)) * 4 + (idx >> 3);
    }

    float c_reg = 0.f;   // cell state: warp 0 lane j<8 owns unit u0+j

    const int tfirst = dir ? (T_LEN - 1) : 0;
    float gx_cur = (lane < 2) ? __ldg(&Gx[(size_t)tfirst * G4 + gxoff]) : 0.f;

    for (int step = 0; step < T_LEN; step++) {
        const int t   = dir ? (T_LEN - 1 - step) : step;
        const int buf = step & 1;

        // prefetch next step's Gx (independent of this step)
        float gx_next = 0.f;
        if (lane < 2 && step + 1 < T_LEN) {
            const int tn = dir ? (t - 1) : (t + 1);
            gx_next = __ldg(&Gx[(size_t)tn * G4 + gxoff]);
        }

        // acquire own packet: poll global, copy VERBATIM into tagged SMEM (no barrier)
        unsigned wtag_h;
        if (step == 0) {
            wtag_h = tagbase + 8191u;
            ((volatile unsigned long long*)h_s8[0])[tid] = ((unsigned long long)wtag_h) << 32;
        } else {
            const int tp = dir ? (t + 1) : (t - 1);
            wtag_h = tagbase + (unsigned)tp;
            const unsigned long long* p = &g_hp[dir][tp][tid];
            unsigned long long v;
            do {
                asm volatile("ld.relaxed.gpu.global.u64 %0, [%1];" : "=l"(v) : "l"(p));
            } while ((unsigned)(v >> 32) != wtag_h);
            ((volatile unsigned long long*)h_s8[buf])[tid] = v;
        }

        // matvec with per-element tag spin: consume h as it lands (overlaps stragglers)
        float a0 = 0.f, a1 = 0.f;
#pragma unroll
        for (int jj = 0; jj < 16; jj++) {
            const volatile unsigned long long* ph = &h_s8[buf][lane + (jj << 5)];
            unsigned long long v;
            do { v = *ph; } while ((unsigned)(v >> 32) != wtag_h);
            const float hv = __uint_as_float((unsigned)v);
            a0 = fmaf(wr0[jj], hv, a0);
            a1 = fmaf(wr1[jj], hv, a1);
        }
        // fold Gx bias in pre-reduce (lane r holds gate bias for row idx0+r)
        if (lane == 0) a0 += gx_cur;
        if (lane == 1) a1 += gx_cur;
        gx_cur = gx_next;
#pragma unroll
        for (int m = 16; m > 0; m >>= 1) {
            a0 += __shfl_xor_sync(0xffffffffu, a0, m);
            a1 += __shfl_xor_sync(0xffffffffu, a1, m);
        }
        if (lane < 2) {
            const unsigned long long gv =
                (((unsigned long long)(unsigned)(step + 1)) << 32) |
                (unsigned long long)__float_as_uint((lane == 0) ? a0 : a1);
            ((volatile unsigned long long*)gates_s8)[idx0 + lane] = gv;
        }

        // warp 0 tail: spin-gather 32 tagged gate words, gates -> c -> h, publish
        if (w == 0) {
            const unsigned gtag = (unsigned)(step + 1);
            const volatile unsigned long long* pg = &gates_s8[lane];
            unsigned long long g;
            do { g = *pg; } while ((unsigned)(g >> 32) != gtag);
            const float x = __uint_as_float((unsigned)g);

            const int q = lane >> 3;
            const float xs = (q == 2) ? 2.f * x : x;
            const float sg = sigmf(xs);
            const float nl = (q == 2) ? (2.f * sg - 1.f) : sg;   // tanh for gate g, sigm else

            const int j = lane & 7;
            const float iv = __shfl_sync(0xffffffffu, nl, j);
            const float fv = __shfl_sync(0xffffffffu, nl, 8 + j);
            const float gv = __shfl_sync(0xffffffffu, nl, 16 + j);
            const float ov = __shfl_sync(0xffffffffu, nl, 24 + j);

            if (lane < 8) {
                const float c = fmaf(fv, c_reg, iv * gv);
                c_reg = c;
                const float hval = ov * (2.f * sigmf(2.f * c) - 1.f);  // o * tanh(c)
                const unsigned long long pkt =
                    ((unsigned long long)(tagbase + (unsigned)t) << 32) |
                    (unsigned long long)__float_as_uint(hval);
                unsigned long long* dst = &g_hp[dir][t][u0 + lane];    // 64B coalesced publish
                asm volatile("st.relaxed.gpu.global.u64 [%0], %1;" :: "l"(dst), "l"(pkt) : "memory");
            }
        }
        // buffer-reuse safety (no barriers needed): overwriting h_s8[buf] for step t+2
        // requires a tag-(t+1) global packet; that requires every producer to have read
        // OUR tag-t packet, which requires all 16 of our warps to have written gates
        // (step t+1)... which per program order follows their step-t reads of h_s8[buf].
        // Same chain covers gates_s8 single-buffering.
    }
}

// ---------------- Kernel 3: out[t][tag] = concat(hs_f[t], hs_b[t]) @ W_out^T + b_out ----
__global__ __launch_bounds__(256) void outproj_kernel(
    const float* __restrict__ Wout, const float* __restrict__ bout, float* __restrict__ out)
{
    __shared__ float xs[4][2 * H_DIM];
    const int tid = threadIdx.x;
    const int t0 = blockIdx.x * 4;

    for (int i = tid; i < 4 * 2 * H_DIM; i += 256) {
        const int tt = i >> 10;
        const int k  = i & 1023;
        const int t  = t0 + tt;
        const unsigned long long pkt = (k < H_DIM) ? g_hp[0][t][k] : g_hp[1][t][k - H_DIM];
        xs[tt][k] = __uint_as_float((unsigned)pkt);
    }
    __syncthreads();

    const int tag = tid & 63;
    const int tt  = tid >> 6;
    if (tag < TAGS) {
        float acc = __ldg(&bout[tag]);
        const float4* __restrict__ wrow = (const float4*)&Wout[(size_t)tag * (2 * H_DIM)];
        const float4* __restrict__ xv   = (const float4*)xs[tt];
#pragma unroll 8
        for (int k4 = 0; k4 < (2 * H_DIM) / 4; k4++) {
            const float4 wv = __ldg(&wrow[k4]);
            const float4 x  = xv[k4];
            acc = fmaf(wv.x, x.x, acc);
            acc = fmaf(wv.y, x.y, acc);
            acc = fmaf(wv.z, x.z, acc);
            acc = fmaf(wv.w, x.w, acc);
        }
        out[(size_t)(t0 + tt) * TAGS + tag] = acc;
    }
}

// ---------------- launch ----------------
extern "C" void kernel_launch(void* const* d_in, const int* in_sizes, int n_in,
                              void* d_out, int out_size)
{
    const int*   sent  = (const int*)d_in[0];
    const float* emb   = (const float*)d_in[1];
    const float* Wih_f = (const float*)d_in[2];
    const float* Whh_f = (const float*)d_in[3];
    const float* bih_f = (const float*)d_in[4];
    const float* bhh_f = (const float*)d_in[5];
    const float* Wih_b = (const float*)d_in[6];
    const float* Whh_b = (const float*)d_in[7];
    const float* bih_b = (const float*)d_in[8];
    const float* bhh_b = (const float*)d_in[9];
    const float* Wout  = (const float*)d_in[10];
    const float* bout  = (const float*)d_in[11];
    float* out = (float*)d_out;

    dim3 gx(G4 / BN, T_LEN / BM, 2);
    xproj_kernel<<<gx, 256>>>(sent, emb, Wih_f, bih_f, bhh_f, Wih_b, bih_b, bhh_b);
    align_dummy_kernel<<<1, 32>>>();
    align_dummy_kernel<<<1, 32>>>();
    lstm_rec_kernel<<<NCTA, 512>>>(Whh_f, Whh_b);
    outproj_kernel<<<T_LEN / 4, 256>>>(Wout, bout, out);
}

// round 16
// speedup vs baseline: 4.6197x; 4.6197x over previous
#include <cuda_runtime.h>
#include <cuda_bf16.h>
#include <cstdint>

#define T_LEN 4096
#define E_DIM 256
#define H_DIM 512
#define G4    2048
#define TAGS  50
#define NCTA  128

// ---------------- device scratch (no allocations allowed) ----------------
__device__ float g_Gx[2][(size_t)T_LEN * G4];            // x-proj, TRANSPOSED: [t][u][gate]
__device__ unsigned long long g_hp[2][T_LEN][H_DIM];     // packets {tag:32 | h:32}, t-major
__device__ unsigned g_epoch;                             // bumped once per launch

// ---------------- Kernel 1: Gx[dir][t][u*4+q] = (emb[sent[t]] @ W_ih^T + b)[q*512+u] ----
#define BM 64
#define BN 64
#define BK 16

__global__ __launch_bounds__(256) void xproj_kernel(
    const int* __restrict__ sent, const float* __restrict__ emb,
    const float* __restrict__ Wih_f, const float* __restrict__ bih_f, const float* __restrict__ bhh_f,
    const float* __restrict__ Wih_b, const float* __restrict__ bih_b, const float* __restrict__ bhh_b)
{
    const int dir = blockIdx.z;
    const float* __restrict__ Wih = dir ? Wih_b : Wih_f;
    const float* __restrict__ bih = dir ? bih_b : bih_f;
    const float* __restrict__ bhh = dir ? bhh_b : bhh_f;
    float* __restrict__ C = g_Gx[dir];

    // bump epoch once per launch (stream-ordered before the recurrence kernel)
    if (blockIdx.x == 0 && blockIdx.y == 0 && dir == 0 && threadIdx.x == 0) {
        g_epoch = g_epoch + 1u;
    }

    __shared__ float As[BK][BM + 4];
    __shared__ float Bs[BK][BN + 4];
    __shared__ int   sidx[BM];

    const int tid = threadIdx.x;
    const int tx = tid & 15;
    const int ty = tid >> 4;
    const int t0 = blockIdx.y * BM;
    const int n0 = blockIdx.x * BN;

    if (tid < BM) sidx[tid] = sent[t0 + tid];
    __syncthreads();

    float acc[4][4];
#pragma unroll
    for (int i = 0; i < 4; i++)
#pragma unroll
        for (int j = 0; j < 4; j++) acc[i][j] = 0.f;

    const int li = tid >> 2;
    const int lk = (tid & 3) * 4;

    for (int k0 = 0; k0 < E_DIM; k0 += BK) {
        const float4 av = *(const float4*)&emb[(size_t)sidx[li] * E_DIM + k0 + lk];
        const float4 bv = *(const float4*)&Wih[(size_t)(n0 + li) * E_DIM + k0 + lk];
        __syncthreads();
        As[lk + 0][li] = av.x; As[lk + 1][li] = av.y; As[lk + 2][li] = av.z; As[lk + 3][li] = av.w;
        Bs[lk + 0][li] = bv.x; Bs[lk + 1][li] = bv.y; Bs[lk + 2][li] = bv.z; Bs[lk + 3][li] = bv.w;
        __syncthreads();
#pragma unroll
        for (int kk = 0; kk < BK; kk++) {
            const float4 a = *(const float4*)&As[kk][ty * 4];
            const float4 b = *(const float4*)&Bs[kk][tx * 4];
            acc[0][0] = fmaf(a.x, b.x, acc[0][0]); acc[0][1] = fmaf(a.x, b.y, acc[0][1]);
            acc[0][2] = fmaf(a.x, b.z, acc[0][2]); acc[0][3] = fmaf(a.x, b.w, acc[0][3]);
            acc[1][0] = fmaf(a.y, b.x, acc[1][0]); acc[1][1] = fmaf(a.y, b.y, acc[1][1]);
            acc[1][2] = fmaf(a.y, b.z, acc[1][2]); acc[1][3] = fmaf(a.y, b.w, acc[1][3]);
            acc[2][0] = fmaf(a.z, b.x, acc[2][0]); acc[2][1] = fmaf(a.z, b.y, acc[2][1]);
            acc[2][2] = fmaf(a.z, b.z, acc[2][2]); acc[2][3] = fmaf(a.z, b.w, acc[2][3]);
            acc[3][0] = fmaf(a.w, b.x, acc[3][0]); acc[3][1] = fmaf(a.w, b.y, acc[3][1]);
            acc[3][2] = fmaf(a.w, b.z, acc[3][2]); acc[3][3] = fmaf(a.w, b.w, acc[3][3]);
        }
    }

    const int n_base = n0 + tx * 4;
    const int q = n_base >> 9;              // gate index (same for all 4 columns: 64 | 512)
    float4 bias;
    bias.x = bih[n_base + 0] + bhh[n_base + 0];
    bias.y = bih[n_base + 1] + bhh[n_base + 1];
    bias.z = bih[n_base + 2] + bhh[n_base + 2];
    bias.w = bih[n_base + 3] + bhh[n_base + 3];
    const int u_base = n_base & 511;
#pragma unroll
    for (int i = 0; i < 4; i++) {
        const int t = t0 + ty * 4 + i;
        float* ct = &C[(size_t)t * G4 + (size_t)u_base * 4 + q];
        ct[0]  = acc[i][0] + bias.x;
        ct[4]  = acc[i][1] + bias.y;
        ct[8]  = acc[i][2] + bias.z;
        ct[12] = acc[i][3] + bias.w;
    }
}

// ---------------- dummy kernel: shifts ncu -s5 capture window onto lstm_rec -------------
__global__ void align_dummy_kernel() {}

// ---------------- Kernel 2: persistent recurrence (R7 core; bar2 -> warp0 gate spin) ----
// sigm(x) = 1/(1+e^-x); tanh(x) = 2*sigm(2x)-1
__device__ __forceinline__ float sigmf(float x) { return 1.f / (1.f + __expf(-x)); }

__global__ __launch_bounds__(512, 1) void lstm_rec_kernel(
    const float* __restrict__ Whhf, const float* __restrict__ Whhb)
{
    const int tid  = threadIdx.x;
    const int lane = tid & 31;
    const int w    = tid >> 5;        // 16 warps
    const int bid  = blockIdx.x;
    const int dir  = bid >> 6;        // 0 = forward, 1 = backward
    const int s    = bid & 63;
    const int u0   = s << 3;          // first of 8 hidden units owned by this CTA

    const float* __restrict__ Whh = dir ? Whhb : Whhf;
    const float* __restrict__ Gx  = g_Gx[dir];

    const unsigned epoch = *((volatile unsigned*)&g_epoch);
    const unsigned tagbase = epoch * 4096u;

    __shared__ float h_s[2][H_DIM];                 // double-buffered h staging (bar1-protected)
    __shared__ unsigned long long gates_s8[32];     // tagged gate sums {step+1 | gate}

    // warp w owns rows idx = w*2 + r, r in {0,1}; gate q = idx>>3; unit j = idx&7
    const int idx0 = w * 2;
    int rows[2];
#pragma unroll
    for (int r = 0; r < 2; r++) {
        const int idx = idx0 + r;
        rows[r] = (idx >> 3) * H_DIM + u0 + (idx & 7);
    }
    float wr0[16], wr1[16];
#pragma unroll
    for (int jj = 0; jj < 16; jj++) {
        wr0[jj] = __ldg(&Whh[(size_t)rows[0] * H_DIM + lane + 32 * jj]);
        wr1[jj] = __ldg(&Whh[(size_t)rows[1] * H_DIM + lane + 32 * jj]);
    }
    // transposed-Gx address for this warp's row r: t*2048 + (u0+(idx&7))*4 + (idx>>3)
    int gxoff = -1;
    if (lane < 2) {
        const int idx = idx0 + lane;
        gxoff = (u0 + (idx & 7)) * 4 + (idx >> 3);
    }

    float c_reg = 0.f;   // cell state: warp 0 lane j<8 owns unit u0+j

    // prefetch Gx for step 0
    const int tfirst = dir ? (T_LEN - 1) : 0;
    float gx_cur = (lane < 2) ? __ldg(&Gx[(size_t)tfirst * G4 + gxoff]) : 0.f;

    for (int step = 0; step < T_LEN; step++) {
        const int t   = dir ? (T_LEN - 1 - step) : step;
        const int buf = step & 1;

        // prefetch next step's Gx (independent of this step)
        float gx_next = 0.f;
        if (lane < 2 && step + 1 < T_LEN) {
            const int tn = dir ? (t - 1) : (t + 1);
            gx_next = __ldg(&Gx[(size_t)tn * G4 + gxoff]);
        }

        // acquire h_{t-1}: each thread polls exactly ONE atomic 64-bit packet {tag|h}
        // (single spin per thread per step, OUTSIDE the compute loop)
        if (step == 0) {
            h_s[0][tid] = 0.f;
        } else {
            const int tp = dir ? (t + 1) : (t - 1);
            const unsigned wtag = tagbase + (unsigned)tp;
            const unsigned long long* p = &g_hp[dir][tp][tid];
            unsigned long long v;
            do {
                asm volatile("ld.relaxed.gpu.global.u64 %0, [%1];" : "=l"(v) : "l"(p));
            } while ((unsigned)(v >> 32) != wtag);
            h_s[buf][tid] = __uint_as_float((unsigned)v);
        }
        __syncthreads();   // bar1 (the ONLY block barrier per step): h_s[buf] complete

        // matvec: plain batchable LDS (no per-element spins!)
        float a0 = 0.f, a1 = 0.f;
#pragma unroll
        for (int jj = 0; jj < 16; jj++) {
            const float hv = h_s[buf][lane + (jj << 5)];
            a0 = fmaf(wr0[jj], hv, a0);
            a1 = fmaf(wr1[jj], hv, a1);
        }
        // fold Gx bias in pre-reduce (lane r holds gate bias for row idx0+r)
        if (lane == 0) a0 += gx_cur;
        if (lane == 1) a1 += gx_cur;
        gx_cur = gx_next;
#pragma unroll
        for (int m = 16; m > 0; m >>= 1) {
            a0 += __shfl_xor_sync(0xffffffffu, a0, m);
            a1 += __shfl_xor_sync(0xffffffffu, a1, m);
        }
        // publish gate sum as a tagged 8B SMEM word (aligned -> single-copy atomic);
        // warps 1-15 then proceed STRAIGHT to the next step (no bar2)
        if (lane < 2) {
            const unsigned long long gword =
                (((unsigned long long)(unsigned)(step + 1)) << 32) |
                (unsigned long long)__float_as_uint((lane == 0) ? a0 : a1);
            ((volatile unsigned long long*)gates_s8)[idx0 + lane] = gword;
        }

        // warp 0 tail: single short spin on 32 tagged gate words, gates -> c -> publish.
        // Reuse hazard: warps overwrite their gate word for step t+2 only after passing
        // bar1(t+1), which requires warp 0's arrival there, which follows these reads.
        if (w == 0) {
            const unsigned gtag = (unsigned)(step + 1);
            const volatile unsigned long long* pg = &gates_s8[lane];
            unsigned long long g;
            do { g = *pg; } while ((unsigned)(g >> 32) != gtag);
            const float x = __uint_as_float((unsigned)g);

            const int q = lane >> 3;
            const float xs = (q == 2) ? 2.f * x : x;
            const float sg = sigmf(xs);
            const float nl = (q == 2) ? (2.f * sg - 1.f) : sg;   // tanh for gate g, sigm else

            const int j = lane & 7;
            const float iv = __shfl_sync(0xffffffffu, nl, j);
            const float fv = __shfl_sync(0xffffffffu, nl, 8 + j);
            const float gv = __shfl_sync(0xffffffffu, nl, 16 + j);
            const float ov = __shfl_sync(0xffffffffu, nl, 24 + j);

            if (lane < 8) {
                const float c = fmaf(fv, c_reg, iv * gv);
                c_reg = c;
                const float hval = ov * (2.f * sigmf(2.f * c) - 1.f);  // o * tanh(c)
                const unsigned long long pkt =
                    ((unsigned long long)(tagbase + (unsigned)t) << 32) |
                    (unsigned long long)__float_as_uint(hval);
                unsigned long long* dst = &g_hp[dir][t][u0 + lane];    // 64B coalesced publish
                asm volatile("st.relaxed.gpu.global.u64 [%0], %1;" :: "l"(dst), "l"(pkt) : "memory");
            }
        }
    }
}

// ---------------- Kernel 3: out[t][tag] = concat(hs_f[t], hs_b[t]) @ W_out^T + b_out ----
__global__ __launch_bounds__(256) void outproj_kernel(
    const float* __restrict__ Wout, const float* __restrict__ bout, float* __restrict__ out)
{
    __shared__ float xs[4][2 * H_DIM];
    const int tid = threadIdx.x;
    const int t0 = blockIdx.x * 4;

    for (int i = tid; i < 4 * 2 * H_DIM; i += 256) {
        const int tt = i >> 10;
        const int k  = i & 1023;
        const int t  = t0 + tt;
        const unsigned long long pkt = (k < H_DIM) ? g_hp[0][t][k] : g_hp[1][t][k - H_DIM];
        xs[tt][k] = __uint_as_float((unsigned)pkt);
    }
    __syncthreads();

    const int tag = tid & 63;
    const int tt  = tid >> 6;
    if (tag < TAGS) {
        float acc = __ldg(&bout[tag]);
        const float4* __restrict__ wrow = (const float4*)&Wout[(size_t)tag * (2 * H_DIM)];
        const float4* __restrict__ xv   = (const float4*)xs[tt];
#pragma unroll 8
        for (int k4 = 0; k4 < (2 * H_DIM) / 4; k4++) {
            const float4 wv = __ldg(&wrow[k4]);
            const float4 x  = xv[k4];
            acc = fmaf(wv.x, x.x, acc);
            acc = fmaf(wv.y, x.y, acc);
            acc = fmaf(wv.z, x.z, acc);
            acc = fmaf(wv.w, x.w, acc);
        }
        out[(size_t)(t0 + tt) * TAGS + tag] = acc;
    }
}

// ---------------- launch ----------------
extern "C" void kernel_launch(void* const* d_in, const int* in_sizes, int n_in,
                              void* d_out, int out_size)
{
    const int*   sent  = (const int*)d_in[0];
    const float* emb   = (const float*)d_in[1];
    const float* Wih_f = (const float*)d_in[2];
    const float* Whh_f = (const float*)d_in[3];
    const float* bih_f = (const float*)d_in[4];
    const float* bhh_f = (const float*)d_in[5];
    const float* Wih_b = (const float*)d_in[6];
    const float* Whh_b = (const float*)d_in[7];
    const float* bih_b = (const float*)d_in[8];
    const float* bhh_b = (const float*)d_in[9];
    const float* Wout  = (const float*)d_in[10];
    const float* bout  = (const float*)d_in[11];
    float* out = (float*)d_out;

    dim3 gx(G4 / BN, T_LEN / BM, 2);
    xproj_kernel<<<gx, 256>>>(sent, emb, Wih_f, bih_f, bhh_f, Wih_b, bih_b, bhh_b);
    align_dummy_kernel<<<1, 32>>>();
    align_dummy_kernel<<<1, 32>>>();
    lstm_rec_kernel<<<NCTA, 512>>>(Whh_f, Whh_b);
    outproj_kernel<<<T_LEN / 4, 256>>>(Wout, bout, out);
}